// round 14
// baseline (speedup 1.0000x reference)
#include <cuda_runtime.h>
#include <cstdint>

// out[n, :] = weight[idx_n, :] where one_hot[n, idx_n] == 1.0
// N = 8192, VOCAB = 8192, D = 1024, fp32.
//
// Two-phase split:
//   Phase 1 (scan): warp-per-row early-exit scan of one_hot (2KB rounds,
//       streaming loads). Finder lane writes idx[row]. ~5.9 TB/s, near floor.
//   Phase 2 (gather): block-per-row, THREAD-per-float4. Each of 256 threads
//       does exactly one LDG.128 + STG.128 -> maximal MLP, no per-warp
//       dependent chains. idx is one uniform load per block.

#define N_ROWS  8192
#define VOCAB   8192
#define DIM     1024
#define WARPS_PER_BLOCK 8
#define THREADS (WARPS_PER_BLOCK * 32)
#define GRID    (N_ROWS / WARPS_PER_BLOCK)    // 1024

__device__ int g_idx[N_ROWS];

// ---------------- Phase 1: find the one-hot position per row ----------------
__global__ __launch_bounds__(THREADS) void scan_kernel(
    const float* __restrict__ one_hot)
{
    const int warp_global = (blockIdx.x * blockDim.x + threadIdx.x) >> 5;
    const int lane = threadIdx.x & 31;
    const unsigned FULL = 0xFFFFFFFFu;

    const uint4* __restrict__ row =
        reinterpret_cast<const uint4*>(one_hot + (size_t)warp_global * VOCAB);

    // 4x uint4 per lane = 2KB per round, 16 rounds max.
    #pragma unroll 1
    for (int base = 0; base < VOCAB / 4; base += 128) {
        uint4 v0 = __ldcs(row + base       + lane);
        uint4 v1 = __ldcs(row + base + 32  + lane);
        uint4 v2 = __ldcs(row + base + 64  + lane);
        uint4 v3 = __ldcs(row + base + 96  + lane);

        unsigned nz0 = (v0.x | v0.y | v0.z | v0.w);
        unsigned nz1 = (v1.x | v1.y | v1.z | v1.w);
        unsigned nz2 = (v2.x | v2.y | v2.z | v2.w);
        unsigned nz3 = (v3.x | v3.y | v3.z | v3.w);

        if (__ballot_sync(FULL, (nz0 | nz1 | nz2 | nz3) != 0u)) {
            // exactly one lane holds the hot element; only it writes
            uint4 v; int chunk;
            if      (nz0) { v = v0; chunk = 0; }
            else if (nz1) { v = v1; chunk = 1; }
            else if (nz2) { v = v2; chunk = 2; }
            else          { v = v3; chunk = 3; }
            if (nz0 | nz1 | nz2 | nz3) {
                int e = (v.x != 0u) ? 0 : (v.y != 0u) ? 1 : (v.z != 0u) ? 2 : 3;
                g_idx[warp_global] = (base + chunk * 32 + lane) * 4 + e;
            }
            break;
        }
    }
}

// ---------------- Phase 2: gather weight rows into out ----------------
// Block-per-row; each of 256 threads moves exactly one float4 (DIM/4 = 256).
__global__ __launch_bounds__(256) void gather_kernel(
    const float* __restrict__ weight,
    float* __restrict__ out)
{
    const int row = blockIdx.x;
    const int tid = threadIdx.x;

    const int idx = g_idx[row];   // uniform per block, one sector, broadcast

    const float4* __restrict__ wrow =
        reinterpret_cast<const float4*>(weight + (size_t)idx * DIM);
    float4* __restrict__ orow =
        reinterpret_cast<float4*>(out + (size_t)row * DIM);

    float4 v = wrow[tid];
    __stcs(orow + tid, v);
}

extern "C" void kernel_launch(void* const* d_in, const int* in_sizes, int n_in,
                              void* d_out, int out_size)
{
    const float* one_hot = (const float*)d_in[0];  // [N, VOCAB] fp32
    const float* weight  = (const float*)d_in[1];  // [VOCAB, D] fp32
    float* out = (float*)d_out;                    // [N, D] fp32

    scan_kernel<<<GRID, THREADS>>>(one_hot);
    gather_kernel<<<N_ROWS, 256>>>(weight, out);
}